// round 8
// baseline (speedup 1.0000x reference)
#include <cuda_runtime.h>
#include <math.h>

#define NATOM 2048
#define NTOK  512
#define CDIM  128
#define CZD   16
#define NHEADS 4
#define CHD   32
#define NBL   3
#define NHID  256
#define NQ    32
#define NKEY  128
#define NQB   (NATOM/NQ)
#define EPS   1e-5f
#define NEGBIG -1e30f
#define NC    (NATOM*CDIM)

// ---------------- scratch ----------------
__device__ float g_maskbias[NATOM];
__device__ float g_lns[NC];
__device__ float g_gate1[NBL*NC];
__device__ float g_shift1[NBL*NC];
__device__ float g_gate2[NBL*NC];
__device__ float g_shift2[NBL*NC];
__device__ float g_og1[NBL*NC];
__device__ float g_og2[NBL*NC];
__device__ float g_pb[NBL*NHEADS*NATOM*NKEY];
__device__ float g_a[NC];
__device__ float g_q[NC];
__device__ float g_k[NC];
__device__ float g_v[NC];
__device__ float g_g[NC];
__device__ float g_ob[NC];
__device__ float g_hidden[NATOM*NHID];

__device__ __forceinline__ float sigm(float x){ return 1.f/(1.f+expf(-x)); }

// ---------------- copy in/out ----------------
__global__ void copy_in_kernel(const float* __restrict__ src){
    int i = blockIdx.x*256 + threadIdx.x;
    g_a[i] = src[i];
}
__global__ void copy_out_kernel(float* __restrict__ dst){
    int i = blockIdx.x*256 + threadIdx.x;
    dst[i] = g_a[i];
}

// ---------------- mask bias ----------------
__global__ void maskbias_kernel(const float* __restrict__ a2t, const float* __restrict__ tm){
    int w = threadIdx.x >> 5, l = threadIdx.x & 31;
    int n = blockIdx.x*8 + w;
    const float* row = a2t + (size_t)n*NTOK;
    float s = 0.f;
    for (int i = l; i < NTOK; i += 32) s += row[i]*tm[i];
    #pragma unroll
    for (int o = 16; o; o >>= 1) s += __shfl_xor_sync(0xffffffffu, s, o);
    if (l == 0) g_maskbias[n] = (s - 1.0f)*1e9f;
}

// ---------------- LN(cl) ----------------
__global__ void ln_cl_kernel(const float* __restrict__ in){
    int w = threadIdx.x >> 5, l = threadIdx.x & 31;
    int base = blockIdx.x*16 + w*4;
    for (int r = 0; r < 4; r++){
        const float* row = in + (size_t)(base+r)*CDIM;
        float x0=row[l], x1=row[l+32], x2=row[l+64], x3=row[l+96];
        float s = x0+x1+x2+x3;
        float s2 = x0*x0+x1*x1+x2*x2+x3*x3;
        #pragma unroll
        for (int o = 16; o; o >>= 1){
            s  += __shfl_xor_sync(0xffffffffu, s, o);
            s2 += __shfl_xor_sync(0xffffffffu, s2, o);
        }
        float mean = s*(1.f/CDIM);
        float var  = s2*(1.f/CDIM) - mean*mean;
        float rstd = rsqrtf(var + EPS);
        float* orow = g_lns + (size_t)(base+r)*CDIM;
        orow[l]    = (x0-mean)*rstd;
        orow[l+32] = (x1-mean)*rstd;
        orow[l+64] = (x2-mean)*rstd;
        orow[l+96] = (x3-mean)*rstd;
    }
}

// ---------------- batched precompute: R7-proven 32-row / 2-col tiles ----------------
__global__ void pre_gemm_kernel(const float* __restrict__ lns, const float* __restrict__ cl,
    const float* __restrict__ a1gs, const float* __restrict__ a1ws,
    const float* __restrict__ a1bs, const float* __restrict__ a1wsb,
    const float* __restrict__ a2gs, const float* __restrict__ a2ws,
    const float* __restrict__ a2bs, const float* __restrict__ a2wsb,
    const float* __restrict__ wog1, const float* __restrict__ bog1,
    const float* __restrict__ wog2, const float* __restrict__ bog2)
{
    int my = blockIdx.y;
    int b = my/6, m = my%6;
    size_t oW = (size_t)b*CDIM*CDIM, o1 = (size_t)b*CDIM, oC = (size_t)b*NC;
    const float* in = lns; const float* gs = 0; const float* W = 0;
    const float* bias = 0; float* out = 0; int sig = 0;
    switch(m){
        case 0: gs=a1gs+o1; W=a1ws +oW; bias=a1bs+o1; sig=1; out=g_gate1 +oC; break;
        case 1: gs=a1gs+o1; W=a1wsb+oW;               sig=0; out=g_shift1+oC; break;
        case 2: gs=a2gs+o1; W=a2ws +oW; bias=a2bs+o1; sig=1; out=g_gate2 +oC; break;
        case 3: gs=a2gs+o1; W=a2wsb+oW;               sig=0; out=g_shift2+oC; break;
        case 4: in=cl; W=wog1+oW; bias=bog1+o1; sig=1; out=g_og1+oC; break;
        default: in=cl; W=wog2+oW; bias=bog2+o1; sig=1; out=g_og2+oC; break;
    }
    __shared__ __align__(16) float ins[32][CDIM];
    int t = threadIdx.x; int m0 = blockIdx.x*32;
    const float4* in4 = (const float4*)in;
    const float4* gs4 = (const float4*)gs;
    for (int idx = t; idx < 32*32; idx += 128){
        int r = idx >> 5, c4 = idx & 31;
        float4 v = in4[(size_t)(m0+r)*32 + c4];
        if (gs){ float4 g = gs4[c4]; v.x*=g.x; v.y*=g.y; v.z*=g.z; v.w*=g.w; }
        *(float4*)&ins[r][c4*4] = v;
    }
    __syncthreads();
    int c0 = (t & 63)*2;
    int rg = (t >> 6)*16;
    float acc0[16], acc1[16];
    #pragma unroll
    for (int i = 0; i < 16; i++){ acc0[i]=0.f; acc1[i]=0.f; }
    for (int k4 = 0; k4 < CDIM/4; k4++){
        float2 w0 = *(const float2*)&W[(k4*4+0)*CDIM + c0];
        float2 w1 = *(const float2*)&W[(k4*4+1)*CDIM + c0];
        float2 w2 = *(const float2*)&W[(k4*4+2)*CDIM + c0];
        float2 w3 = *(const float2*)&W[(k4*4+3)*CDIM + c0];
        #pragma unroll
        for (int i = 0; i < 16; i++){
            float4 a = *(const float4*)&ins[rg+i][k4*4];
            acc0[i] = fmaf(a.x, w0.x, fmaf(a.y, w1.x, fmaf(a.z, w2.x, fmaf(a.w, w3.x, acc0[i]))));
            acc1[i] = fmaf(a.x, w0.y, fmaf(a.y, w1.y, fmaf(a.z, w2.y, fmaf(a.w, w3.y, acc1[i]))));
        }
    }
    float b0 = bias ? bias[c0] : 0.f;
    float b1 = bias ? bias[c0+1] : 0.f;
    #pragma unroll
    for (int i = 0; i < 16; i++){
        float v0 = acc0[i] + b0, v1 = acc1[i] + b1;
        if (sig){ v0 = sigm(v0); v1 = sigm(v1); }
        float* o = out + (size_t)(m0+rg+i)*CDIM + c0;
        o[0] = v0; o[1] = v1;
    }
}

// ---------------- pair bias (mask + window folded) ----------------
__global__ void pb_kernel(const float* __restrict__ plm, const float* __restrict__ gz,
                          const float* __restrict__ bz, const float* __restrict__ wz){
    __shared__ float wzc[CZD][12];
    __shared__ float bzd[12];
    int t = threadIdx.x;
    if (t < CZD*12){
        int c = t/12, idx = t%12, b = idx>>2, h = idx&3;
        wzc[c][idx] = gz[b*CZD + c]*wz[(b*CZD + c)*4 + h];
    }
    if (t < 12){
        int b = t>>2, h = t&3; float s = 0.f;
        for (int c = 0; c < CZD; c++) s += bz[b*CZD + c]*wz[(b*CZD + c)*4 + h];
        bzd[t] = s;
    }
    __syncthreads();
    int gid = blockIdx.x*256 + t;
    int n = gid >> 7, slot = gid & 127;
    int m = (n & ~31) - 48 + slot;
    if (m < 0 || m >= NATOM){
        #pragma unroll
        for (int idx = 0; idx < 12; idx++)
            g_pb[((size_t)idx*NATOM + n)*NKEY + slot] = NEGBIG;
        return;
    }
    const float4* p = (const float4*)(plm + ((size_t)n*NATOM + m)*CZD);
    float x[16];
    float4 f;
    f = p[0]; x[0]=f.x; x[1]=f.y; x[2]=f.z; x[3]=f.w;
    f = p[1]; x[4]=f.x; x[5]=f.y; x[6]=f.z; x[7]=f.w;
    f = p[2]; x[8]=f.x; x[9]=f.y; x[10]=f.z; x[11]=f.w;
    f = p[3]; x[12]=f.x; x[13]=f.y; x[14]=f.z; x[15]=f.w;
    float s = 0.f, s2 = 0.f;
    #pragma unroll
    for (int c = 0; c < 16; c++){ s += x[c]; s2 += x[c]*x[c]; }
    float mean = s*(1.f/16.f);
    float var  = s2*(1.f/16.f) - mean*mean;
    float rstd = rsqrtf(var + EPS);
    float val[12];
    #pragma unroll
    for (int idx = 0; idx < 12; idx++) val[idx] = 0.f;
    #pragma unroll
    for (int c = 0; c < 16; c++){
        float z = (x[c]-mean)*rstd;
        #pragma unroll
        for (int idx = 0; idx < 12; idx++) val[idx] += z*wzc[c][idx];
    }
    float mb = g_maskbias[m];
    #pragma unroll
    for (int idx = 0; idx < 12; idx++)
        g_pb[((size_t)idx*NATOM + n)*NKEY + slot] = val[idx] + bzd[idx] + mb;
}

// ---------------- per-block: AdaLN + {q,k,v,g, trans1-lo, trans1-hi} ----------------
// grid (128, 6); mats 0-3 use gate1/shift1 -> q,k,v,g; mats 4-5 use gate2/shift2 ->
// SwiGLU hidden halves (independent of attention, overlapped here).
__global__ void adaln_proj_kernel(const float* __restrict__ gate1, const float* __restrict__ shift1,
                                  const float* __restrict__ gate2, const float* __restrict__ shift2,
                                  const float* __restrict__ wq, const float* __restrict__ bq,
                                  const float* __restrict__ wk, const float* __restrict__ wv,
                                  const float* __restrict__ wg,
                                  const float* __restrict__ wt1, const float* __restrict__ wt2){
    __shared__ float als[16][CDIM];
    int t = threadIdx.x; int m0 = blockIdx.x*16;
    int mat = blockIdx.y;
    int w = t >> 5, l = t & 31;
    const float* gate  = (mat < 4) ? gate1  : gate2;
    const float* shift = (mat < 4) ? shift1 : shift2;
    for (int idx = t; idx < 16*CDIM; idx += 128){
        int r = idx >> 7, c = idx & 127;
        als[r][c] = g_a[(size_t)(m0+r)*CDIM + c];
    }
    __syncthreads();
    for (int r = 0; r < 4; r++){
        int i = w*4 + r; int n = m0 + i;
        float x0=als[i][l], x1=als[i][l+32], x2=als[i][l+64], x3=als[i][l+96];
        float s = x0+x1+x2+x3;
        float s2 = x0*x0+x1*x1+x2*x2+x3*x3;
        #pragma unroll
        for (int o = 16; o; o >>= 1){
            s  += __shfl_xor_sync(0xffffffffu, s, o);
            s2 += __shfl_xor_sync(0xffffffffu, s2, o);
        }
        float mean = s*(1.f/CDIM);
        float var  = s2*(1.f/CDIM) - mean*mean;
        float rstd = rsqrtf(var + EPS);
        float a0=(x0-mean)*rstd, a1=(x1-mean)*rstd, a2=(x2-mean)*rstd, a3=(x3-mean)*rstd;
        size_t nb = (size_t)n*CDIM;
        als[i][l]    = gate[nb+l]   *a0 + shift[nb+l];
        als[i][l+32] = gate[nb+l+32]*a1 + shift[nb+l+32];
        als[i][l+64] = gate[nb+l+64]*a2 + shift[nb+l+64];
        als[i][l+96] = gate[nb+l+96]*a3 + shift[nb+l+96];
    }
    __syncthreads();
    if (mat < 4){
        const float* W; float* O;
        switch(mat){
            case 0: W = wq; O = g_q; break;
            case 1: W = wk; O = g_k; break;
            case 2: W = wv; O = g_v; break;
            default: W = wg; O = g_g; break;
        }
        float acc[16];
        #pragma unroll
        for (int i = 0; i < 16; i++) acc[i] = 0.f;
        #pragma unroll 2
        for (int k4 = 0; k4 < CDIM/4; k4++){
            float w0 = W[(k4*4+0)*CDIM + t];
            float w1 = W[(k4*4+1)*CDIM + t];
            float w2 = W[(k4*4+2)*CDIM + t];
            float w3 = W[(k4*4+3)*CDIM + t];
            #pragma unroll
            for (int i = 0; i < 16; i++){
                float4 a = *(const float4*)&als[i][k4*4];
                acc[i] = fmaf(a.x, w0, fmaf(a.y, w1, fmaf(a.z, w2, fmaf(a.w, w3, acc[i]))));
            }
        }
        float bb = (mat == 0) ? bq[t] : 0.f;
        #pragma unroll
        for (int i = 0; i < 16; i++){
            float v = acc[i] + bb;
            if (mat == 3) v = sigm(v);
            O[(size_t)(m0+i)*CDIM + t] = v;
        }
    } else {
        int c = t + (mat-4)*128;      // hidden column 0..255
        float acc1[16], acc2[16];
        #pragma unroll
        for (int i = 0; i < 16; i++){ acc1[i]=0.f; acc2[i]=0.f; }
        #pragma unroll 2
        for (int k4 = 0; k4 < CDIM/4; k4++){
            float w10 = wt1[(k4*4+0)*NHID + c], w20 = wt2[(k4*4+0)*NHID + c];
            float w11 = wt1[(k4*4+1)*NHID + c], w21 = wt2[(k4*4+1)*NHID + c];
            float w12 = wt1[(k4*4+2)*NHID + c], w22 = wt2[(k4*4+2)*NHID + c];
            float w13 = wt1[(k4*4+3)*NHID + c], w23 = wt2[(k4*4+3)*NHID + c];
            #pragma unroll
            for (int i = 0; i < 16; i++){
                float4 a = *(const float4*)&als[i][k4*4];
                acc1[i] = fmaf(a.x, w10, fmaf(a.y, w11, fmaf(a.z, w12, fmaf(a.w, w13, acc1[i]))));
                acc2[i] = fmaf(a.x, w20, fmaf(a.y, w21, fmaf(a.z, w22, fmaf(a.w, w23, acc2[i]))));
            }
        }
        #pragma unroll
        for (int i = 0; i < 16; i++){
            float h1 = acc1[i];
            g_hidden[(size_t)(m0+i)*NHID + c] = h1*sigm(h1)*acc2[i];
        }
    }
}

// ---------------- block-sparse attention (R3 proven version) ----------------
__global__ void attn_kernel(const float* __restrict__ pb){
    __shared__ __align__(16) float qs[32][32];
    __shared__ __align__(16) float vs[128][32];
    __shared__ __align__(16) float buf[128*32];
    int t = threadIdx.x;
    int j = blockIdx.x, h = blockIdx.y;
    int n0 = j*NQ, w0 = j*NQ - 48, hd0 = h*CHD;
    for (int idx = t; idx < 32*32; idx += 128){
        int i = idx >> 5, d = idx & 31;
        qs[i][d] = g_q[(size_t)(n0+i)*CDIM + hd0 + d];
    }
    for (int idx = t; idx < 128*32; idx += 128){
        int m = idx >> 5, d = idx & 31;
        int key = w0 + m;
        float kk = 0.f, vv = 0.f;
        if (key >= 0 && key < NATOM){
            kk = g_k[(size_t)key*CDIM + hd0 + d];
            vv = g_v[(size_t)key*CDIM + hd0 + d];
        }
        buf[m*32 + d] = kk; vs[m][d] = vv;
    }
    __syncthreads();
    float kr[32];
    #pragma unroll
    for (int d = 0; d < 32; d++) kr[d] = buf[t*32 + d];
    __syncthreads();
    const float scale = 0.17677669529663687f;
    const float* pbr = pb + (size_t)h*NATOM*NKEY + (size_t)n0*NKEY;
    #pragma unroll 4
    for (int i = 0; i < 32; i++){
        float acc = 0.f;
        #pragma unroll
        for (int d4 = 0; d4 < 8; d4++){
            float4 q = *(const float4*)&qs[i][d4*4];
            acc = fmaf(q.x, kr[d4*4+0], fmaf(q.y, kr[d4*4+1],
                  fmaf(q.z, kr[d4*4+2], fmaf(q.w, kr[d4*4+3], acc))));
        }
        buf[i*128 + t] = acc*scale + pbr[i*NKEY + t];
    }
    __syncthreads();
    int w = t >> 5, l = t & 31;
    for (int r = 0; r < 8; r++){
        int i = w*8 + r;
        float x0=buf[i*128+l], x1=buf[i*128+l+32], x2=buf[i*128+l+64], x3=buf[i*128+l+96];
        float mx = fmaxf(fmaxf(x0,x1), fmaxf(x2,x3));
        #pragma unroll
        for (int o = 16; o; o >>= 1) mx = fmaxf(mx, __shfl_xor_sync(0xffffffffu, mx, o));
        float e0=expf(x0-mx), e1=expf(x1-mx), e2=expf(x2-mx), e3=expf(x3-mx);
        float s = e0+e1+e2+e3;
        #pragma unroll
        for (int o = 16; o; o >>= 1) s += __shfl_xor_sync(0xffffffffu, s, o);
        float inv = 1.f/s;
        buf[i*128+l]=e0*inv; buf[i*128+l+32]=e1*inv; buf[i*128+l+64]=e2*inv; buf[i*128+l+96]=e3*inv;
    }
    __syncthreads();
    int i = t >> 2, d0 = (t & 3)*8;
    float acc[8];
    #pragma unroll
    for (int dd = 0; dd < 8; dd++) acc[dd] = 0.f;
    #pragma unroll 4
    for (int kk = 0; kk < 128; kk++){
        float wgt = buf[i*128 + kk];
        float4 v0 = *(const float4*)&vs[kk][d0];
        float4 v1 = *(const float4*)&vs[kk][d0+4];
        acc[0] = fmaf(wgt, v0.x, acc[0]); acc[1] = fmaf(wgt, v0.y, acc[1]);
        acc[2] = fmaf(wgt, v0.z, acc[2]); acc[3] = fmaf(wgt, v0.w, acc[3]);
        acc[4] = fmaf(wgt, v1.x, acc[4]); acc[5] = fmaf(wgt, v1.y, acc[5]);
        acc[6] = fmaf(wgt, v1.z, acc[6]); acc[7] = fmaf(wgt, v1.w, acc[7]);
    }
    int n = n0 + i;
    #pragma unroll
    for (int dd = 0; dd < 8; dd++){
        int c = hd0 + d0 + dd;
        g_ob[(size_t)n*CDIM + c] = g_g[(size_t)n*CDIM + c]*acc[dd];
    }
}

// ---------------- light tail: outproj*og1 + trans2*og2 + residual ----------------
// 8 rows, 256 threads; two independent GEMMs, one sync.
__global__ void tail_kernel(const float* __restrict__ wo, const float* __restrict__ og1,
                            const float* __restrict__ wt3, const float* __restrict__ og2){
    __shared__ __align__(16) float obs[8][CDIM];
    __shared__ __align__(16) float hid[8][NHID];
    int t = threadIdx.x;               // 256
    int m0 = blockIdx.x*8;
    for (int idx = t; idx < 8*CDIM/4; idx += 256){
        int r = idx >> 5, c4 = idx & 31;
        *(float4*)&obs[r][c4*4] = *(const float4*)(g_ob + (size_t)(m0+r)*CDIM + c4*4);
    }
    for (int idx = t; idx < 8*NHID/4; idx += 256){
        int r = idx >> 6, c4 = idx & 63;
        *(float4*)&hid[r][c4*4] = *(const float4*)(g_hidden + (size_t)(m0+r)*NHID + c4*4);
    }
    __syncthreads();
    int col = t & 127, half = t >> 7;
    int r0 = half*4;
    float attr[4];
    // phase A: outproj (k=128)
    {
        float acc[4] = {0.f,0.f,0.f,0.f};
        #pragma unroll 2
        for (int k4 = 0; k4 < CDIM/4; k4++){
            float w0 = wo[(k4*4+0)*CDIM + col];
            float w1 = wo[(k4*4+1)*CDIM + col];
            float w2 = wo[(k4*4+2)*CDIM + col];
            float w3 = wo[(k4*4+3)*CDIM + col];
            #pragma unroll
            for (int i = 0; i < 4; i++){
                float4 a = *(const float4*)&obs[r0+i][k4*4];
                acc[i] = fmaf(a.x, w0, fmaf(a.y, w1, fmaf(a.z, w2, fmaf(a.w, w3, acc[i]))));
            }
        }
        size_t ob = (size_t)(m0+r0)*CDIM + col;
        attr[0] = og1[ob         ]*acc[0];
        attr[1] = og1[ob +   CDIM]*acc[1];
        attr[2] = og1[ob + 2*CDIM]*acc[2];
        attr[3] = og1[ob + 3*CDIM]*acc[3];
    }
    // phase C: trans2 (k=256) + combine
    {
        float acc[4] = {0.f,0.f,0.f,0.f};
        #pragma unroll 2
        for (int k4 = 0; k4 < NHID/4; k4++){
            float w0 = wt3[(k4*4+0)*CDIM + col];
            float w1 = wt3[(k4*4+1)*CDIM + col];
            float w2 = wt3[(k4*4+2)*CDIM + col];
            float w3 = wt3[(k4*4+3)*CDIM + col];
            #pragma unroll
            for (int i = 0; i < 4; i++){
                float4 a = *(const float4*)&hid[r0+i][k4*4];
                acc[i] = fmaf(a.x, w0, fmaf(a.y, w1, fmaf(a.z, w2, fmaf(a.w, w3, acc[i]))));
            }
        }
        size_t ob = (size_t)(m0+r0)*CDIM + col;
        g_a[ob         ] = attr[0] + og2[ob         ]*acc[0];
        g_a[ob +   CDIM] = attr[1] + og2[ob +   CDIM]*acc[1];
        g_a[ob + 2*CDIM] = attr[2] + og2[ob + 2*CDIM]*acc[2];
        g_a[ob + 3*CDIM] = attr[3] + og2[ob + 3*CDIM]*acc[3];
    }
}

// ---------------- host launcher ----------------
extern "C" void kernel_launch(void* const* d_in, const int* in_sizes, int n_in,
                              void* d_out, int out_size){
    const float* ql       = (const float*)d_in[0];
    const float* cl       = (const float*)d_in[1];
    const float* plm      = (const float*)d_in[2];
    const float* a2t      = (const float*)d_in[3];
    const float* tm       = (const float*)d_in[4];
    const float* ada1_gs  = (const float*)d_in[5];
    const float* ada1_ws  = (const float*)d_in[6];
    const float* ada1_bs  = (const float*)d_in[7];
    const float* ada1_wsb = (const float*)d_in[8];
    const float* wq       = (const float*)d_in[9];
    const float* bq       = (const float*)d_in[10];
    const float* wk       = (const float*)d_in[11];
    const float* wv       = (const float*)d_in[12];
    const float* gz       = (const float*)d_in[13];
    const float* bz       = (const float*)d_in[14];
    const float* wz       = (const float*)d_in[15];
    const float* wg       = (const float*)d_in[16];
    const float* wo       = (const float*)d_in[17];
    const float* wog1     = (const float*)d_in[18];
    const float* bog1     = (const float*)d_in[19];
    const float* ada2_gs  = (const float*)d_in[20];
    const float* ada2_ws  = (const float*)d_in[21];
    const float* ada2_bs  = (const float*)d_in[22];
    const float* ada2_wsb = (const float*)d_in[23];
    const float* wt1      = (const float*)d_in[24];
    const float* wt2      = (const float*)d_in[25];
    const float* wt3      = (const float*)d_in[26];
    const float* wog2     = (const float*)d_in[27];
    const float* bog2     = (const float*)d_in[28];

    float *p_lns, *p_gate1, *p_shift1, *p_gate2, *p_shift2, *p_og1, *p_og2, *p_pb;
    cudaGetSymbolAddress((void**)&p_lns,    g_lns);
    cudaGetSymbolAddress((void**)&p_gate1,  g_gate1);
    cudaGetSymbolAddress((void**)&p_shift1, g_shift1);
    cudaGetSymbolAddress((void**)&p_gate2,  g_gate2);
    cudaGetSymbolAddress((void**)&p_shift2, g_shift2);
    cudaGetSymbolAddress((void**)&p_og1,    g_og1);
    cudaGetSymbolAddress((void**)&p_og2,    g_og2);
    cudaGetSymbolAddress((void**)&p_pb,     g_pb);

    copy_in_kernel<<<NC/256, 256>>>(ql);
    ln_cl_kernel<<<NATOM/16, 128>>>(cl);
    maskbias_kernel<<<NATOM/8, 256>>>(a2t, tm);

    dim3 pg(NATOM/32, 18);
    pre_gemm_kernel<<<pg, 128>>>(p_lns, cl,
        ada1_gs, ada1_ws, ada1_bs, ada1_wsb,
        ada2_gs, ada2_ws, ada2_bs, ada2_wsb,
        wog1, bog1, wog2, bog2);

    pb_kernel<<<NATOM*NKEY/256, 256>>>(plm, gz, bz, wz);

    for (int b = 0; b < NBL; b++){
        size_t oC = (size_t)b*NC, oW = (size_t)b*CDIM*CDIM;
        dim3 qg(NATOM/16, 6);
        adaln_proj_kernel<<<qg, 128>>>(p_gate1+oC, p_shift1+oC, p_gate2+oC, p_shift2+oC,
                                       wq+oW, bq+(size_t)b*CDIM, wk+oW, wv+oW, wg+oW,
                                       wt1+(size_t)b*CDIM*NHID, wt2+(size_t)b*CDIM*NHID);
        dim3 ag(NQB, NHEADS);
        attn_kernel<<<ag, 128>>>(p_pb + (size_t)b*NHEADS*NATOM*NKEY);
        tail_kernel<<<NATOM/8, 256>>>(wo+oW, p_og1+oC,
                                      wt3+(size_t)b*NHID*CDIM, p_og2+oC);
    }
    copy_out_kernel<<<NC/256, 256>>>((float*)d_out);
}

// round 9
// speedup vs baseline: 1.1761x; 1.1761x over previous
#include <cuda_runtime.h>
#include <math.h>

#define NATOM 2048
#define NTOK  512
#define CDIM  128
#define CZD   16
#define NHEADS 4
#define CHD   32
#define NBL   3
#define NHID  256
#define NQ    32
#define NKEY  128
#define NQB   (NATOM/NQ)
#define EPS   1e-5f
#define NEGBIG -1e30f
#define NC    (NATOM*CDIM)

#define COPY_CTAS (NC/256)       /* 1024 */
#define MB_CTAS   (NATOM/8)      /* 256 */
#define PRE_CTAS  (18*64)        /* 1152 */
#define PB_CTAS   NATOM          /* 2048 */

// ---------------- scratch ----------------
__device__ float g_maskbias[NATOM];
__device__ float g_gate1[NBL*NC];
__device__ float g_shift1[NBL*NC];
__device__ float g_gate2[NBL*NC];
__device__ float g_shift2[NBL*NC];
__device__ float g_og1[NBL*NC];
__device__ float g_og2[NBL*NC];
__device__ float g_pb[NBL*NHEADS*NATOM*NKEY];
__device__ float g_a[NC];
__device__ float g_q[NC];
__device__ float g_k[NC];
__device__ float g_v[NC];
__device__ float g_g[NC];
__device__ float g_ob[NC];
__device__ float g_hidden[NATOM*NHID];

__device__ __forceinline__ float sigm(float x){ return 1.f/(1.f+expf(-x)); }

// ---------------- prep: copy_in + maskbias ----------------
__global__ void prep_kernel(const float* __restrict__ ql,
                            const float* __restrict__ a2t, const float* __restrict__ tm){
    int x = blockIdx.x, t = threadIdx.x;
    if (x < COPY_CTAS){
        int i = x*256 + t;
        g_a[i] = ql[i];
    } else {
        int w = t >> 5, l = t & 31;
        int n = (x - COPY_CTAS)*8 + w;
        const float* row = a2t + (size_t)n*NTOK;
        float s = 0.f;
        for (int i = l; i < NTOK; i += 32) s += row[i]*tm[i];
        #pragma unroll
        for (int o = 16; o; o >>= 1) s += __shfl_xor_sync(0xffffffffu, s, o);
        if (l == 0) g_maskbias[n] = (s - 1.0f)*1e9f;
    }
}

// ---------------- stage2: 18 precompute GEMMs (LN inline) UNION pair-bias ----------
__global__ void __launch_bounds__(128) stage2_kernel(
    const float* __restrict__ cl, const float* __restrict__ plm,
    const float* __restrict__ gz, const float* __restrict__ bz, const float* __restrict__ wz,
    const float* __restrict__ a1gs, const float* __restrict__ a1ws,
    const float* __restrict__ a1bs, const float* __restrict__ a1wsb,
    const float* __restrict__ a2gs, const float* __restrict__ a2ws,
    const float* __restrict__ a2bs, const float* __restrict__ a2wsb,
    const float* __restrict__ wog1, const float* __restrict__ bog1,
    const float* __restrict__ wog2, const float* __restrict__ bog2)
{
    int t = threadIdx.x;
    if (blockIdx.x < PRE_CTAS){
        int my = blockIdx.x / 64;
        int tile = blockIdx.x % 64;
        int b = my/6, m = my%6;
        size_t oW = (size_t)b*CDIM*CDIM, o1 = (size_t)b*CDIM, oC = (size_t)b*NC;
        const float* gs = 0; const float* W = 0;
        const float* bias = 0; float* out = 0; int sig = 0; int doLN = (m < 4);
        switch(m){
            case 0: gs=a1gs+o1; W=a1ws +oW; bias=a1bs+o1; sig=1; out=g_gate1 +oC; break;
            case 1: gs=a1gs+o1; W=a1wsb+oW;               sig=0; out=g_shift1+oC; break;
            case 2: gs=a2gs+o1; W=a2ws +oW; bias=a2bs+o1; sig=1; out=g_gate2 +oC; break;
            case 3: gs=a2gs+o1; W=a2wsb+oW;               sig=0; out=g_shift2+oC; break;
            case 4: W=wog1+oW; bias=bog1+o1; sig=1; out=g_og1+oC; break;
            default: W=wog2+oW; bias=bog2+o1; sig=1; out=g_og2+oC; break;
        }
        __shared__ __align__(16) float ins[32][CDIM];
        int m0 = tile*32;
        const float4* in4 = (const float4*)cl;
        for (int idx = t; idx < 32*32; idx += 128){
            int r = idx >> 5, c4 = idx & 31;
            *(float4*)&ins[r][c4*4] = in4[(size_t)(m0+r)*32 + c4];
        }
        __syncthreads();
        if (doLN){
            int w = t >> 5, l = t & 31;
            for (int r8 = 0; r8 < 8; r8++){
                int r = w*8 + r8;
                float x0=ins[r][l], x1=ins[r][l+32], x2=ins[r][l+64], x3=ins[r][l+96];
                float s = x0+x1+x2+x3;
                float s2 = x0*x0+x1*x1+x2*x2+x3*x3;
                #pragma unroll
                for (int o = 16; o; o >>= 1){
                    s  += __shfl_xor_sync(0xffffffffu, s, o);
                    s2 += __shfl_xor_sync(0xffffffffu, s2, o);
                }
                float mean = s*(1.f/CDIM);
                float var  = s2*(1.f/CDIM) - mean*mean;
                float rstd = rsqrtf(var + EPS);
                ins[r][l]    = (x0-mean)*rstd*gs[l];
                ins[r][l+32] = (x1-mean)*rstd*gs[l+32];
                ins[r][l+64] = (x2-mean)*rstd*gs[l+64];
                ins[r][l+96] = (x3-mean)*rstd*gs[l+96];
            }
            __syncthreads();
        }
        int c0 = (t & 63)*2;
        int rg = (t >> 6)*16;
        float acc0[16], acc1[16];
        #pragma unroll
        for (int i = 0; i < 16; i++){ acc0[i]=0.f; acc1[i]=0.f; }
        for (int k4 = 0; k4 < CDIM/4; k4++){
            float2 w0 = *(const float2*)&W[(k4*4+0)*CDIM + c0];
            float2 w1 = *(const float2*)&W[(k4*4+1)*CDIM + c0];
            float2 w2 = *(const float2*)&W[(k4*4+2)*CDIM + c0];
            float2 w3 = *(const float2*)&W[(k4*4+3)*CDIM + c0];
            #pragma unroll
            for (int i = 0; i < 16; i++){
                float4 a = *(const float4*)&ins[rg+i][k4*4];
                acc0[i] = fmaf(a.x, w0.x, fmaf(a.y, w1.x, fmaf(a.z, w2.x, fmaf(a.w, w3.x, acc0[i]))));
                acc1[i] = fmaf(a.x, w0.y, fmaf(a.y, w1.y, fmaf(a.z, w2.y, fmaf(a.w, w3.y, acc1[i]))));
            }
        }
        float b0 = bias ? bias[c0] : 0.f;
        float b1 = bias ? bias[c0+1] : 0.f;
        #pragma unroll
        for (int i = 0; i < 16; i++){
            float v0 = acc0[i] + b0, v1 = acc1[i] + b1;
            if (sig){ v0 = sigm(v0); v1 = sigm(v1); }
            float* o = out + (size_t)(m0+rg+i)*CDIM + c0;
            o[0] = v0; o[1] = v1;
        }
    } else {
        __shared__ float wzc[CZD][12];
        __shared__ float bzd[12];
        for (int idx = t; idx < CZD*12; idx += 128){
            int c = idx/12, id = idx%12, b = id>>2, h = id&3;
            wzc[c][id] = gz[b*CZD + c]*wz[(b*CZD + c)*4 + h];
        }
        if (t < 12){
            int b = t>>2, h = t&3; float s = 0.f;
            for (int c = 0; c < CZD; c++) s += bz[b*CZD + c]*wz[(b*CZD + c)*4 + h];
            bzd[t] = s;
        }
        __syncthreads();
        int n = blockIdx.x - PRE_CTAS;
        int slot = t;
        int m = (n & ~31) - 48 + slot;
        if (m < 0 || m >= NATOM){
            #pragma unroll
            for (int idx = 0; idx < 12; idx++)
                g_pb[((size_t)idx*NATOM + n)*NKEY + slot] = NEGBIG;
            return;
        }
        const float4* p = (const float4*)(plm + ((size_t)n*NATOM + m)*CZD);
        float x[16];
        float4 f;
        f = p[0]; x[0]=f.x; x[1]=f.y; x[2]=f.z; x[3]=f.w;
        f = p[1]; x[4]=f.x; x[5]=f.y; x[6]=f.z; x[7]=f.w;
        f = p[2]; x[8]=f.x; x[9]=f.y; x[10]=f.z; x[11]=f.w;
        f = p[3]; x[12]=f.x; x[13]=f.y; x[14]=f.z; x[15]=f.w;
        float s = 0.f, s2 = 0.f;
        #pragma unroll
        for (int c = 0; c < 16; c++){ s += x[c]; s2 += x[c]*x[c]; }
        float mean = s*(1.f/16.f);
        float var  = s2*(1.f/16.f) - mean*mean;
        float rstd = rsqrtf(var + EPS);
        float val[12];
        #pragma unroll
        for (int idx = 0; idx < 12; idx++) val[idx] = 0.f;
        #pragma unroll
        for (int c = 0; c < 16; c++){
            float z = (x[c]-mean)*rstd;
            #pragma unroll
            for (int idx = 0; idx < 12; idx++) val[idx] += z*wzc[c][idx];
        }
        float mb = g_maskbias[m];
        #pragma unroll
        for (int idx = 0; idx < 12; idx++)
            g_pb[((size_t)idx*NATOM + n)*NKEY + slot] = val[idx] + bzd[idx] + mb;
    }
}

// ---------------- per-block: AdaLN + {q,k,v,g} (R3-proven) -------------------------
__global__ void adaln_proj_kernel(const float* __restrict__ gate1, const float* __restrict__ shift1,
                                  const float* __restrict__ wq, const float* __restrict__ bq,
                                  const float* __restrict__ wk, const float* __restrict__ wv,
                                  const float* __restrict__ wg){
    __shared__ __align__(16) float als[16][CDIM];
    int t = threadIdx.x; int m0 = blockIdx.x*16;
    int mat = blockIdx.y;
    int w = t >> 5, l = t & 31;
    for (int idx = t; idx < 16*CDIM; idx += 128){
        int r = idx >> 7, c = idx & 127;
        als[r][c] = g_a[(size_t)(m0+r)*CDIM + c];
    }
    __syncthreads();
    for (int r = 0; r < 4; r++){
        int i = w*4 + r; int n = m0 + i;
        float x0=als[i][l], x1=als[i][l+32], x2=als[i][l+64], x3=als[i][l+96];
        float s = x0+x1+x2+x3;
        float s2 = x0*x0+x1*x1+x2*x2+x3*x3;
        #pragma unroll
        for (int o = 16; o; o >>= 1){
            s  += __shfl_xor_sync(0xffffffffu, s, o);
            s2 += __shfl_xor_sync(0xffffffffu, s2, o);
        }
        float mean = s*(1.f/CDIM);
        float var  = s2*(1.f/CDIM) - mean*mean;
        float rstd = rsqrtf(var + EPS);
        float a0=(x0-mean)*rstd, a1=(x1-mean)*rstd, a2=(x2-mean)*rstd, a3=(x3-mean)*rstd;
        size_t nb = (size_t)n*CDIM;
        als[i][l]    = gate1[nb+l]   *a0 + shift1[nb+l];
        als[i][l+32] = gate1[nb+l+32]*a1 + shift1[nb+l+32];
        als[i][l+64] = gate1[nb+l+64]*a2 + shift1[nb+l+64];
        als[i][l+96] = gate1[nb+l+96]*a3 + shift1[nb+l+96];
    }
    __syncthreads();
    const float* W; float* O;
    switch(mat){
        case 0: W = wq; O = g_q; break;
        case 1: W = wk; O = g_k; break;
        case 2: W = wv; O = g_v; break;
        default: W = wg; O = g_g; break;
    }
    float acc[16];
    #pragma unroll
    for (int i = 0; i < 16; i++) acc[i] = 0.f;
    #pragma unroll 2
    for (int k4 = 0; k4 < CDIM/4; k4++){
        float w0 = W[(k4*4+0)*CDIM + t];
        float w1 = W[(k4*4+1)*CDIM + t];
        float w2 = W[(k4*4+2)*CDIM + t];
        float w3 = W[(k4*4+3)*CDIM + t];
        #pragma unroll
        for (int i = 0; i < 16; i++){
            float4 a = *(const float4*)&als[i][k4*4];
            acc[i] = fmaf(a.x, w0, fmaf(a.y, w1, fmaf(a.z, w2, fmaf(a.w, w3, acc[i]))));
        }
    }
    float bb = (mat == 0) ? bq[t] : 0.f;
    #pragma unroll
    for (int i = 0; i < 16; i++){
        float v = acc[i] + bb;
        if (mat == 3) v = sigm(v);
        O[(size_t)(m0+i)*CDIM + t] = v;
    }
}

// ---------------- union: attention (x<256) + trans1 (x>=256) ----------------------
__global__ void __launch_bounds__(128) mid_kernel(const float* __restrict__ pb,
                           const float* __restrict__ gate2, const float* __restrict__ shift2,
                           const float* __restrict__ wt1, const float* __restrict__ wt2){
    int t = threadIdx.x;
    if (blockIdx.x < 256){
        __shared__ __align__(16) float qs[32][32];
        __shared__ __align__(16) float vs[128][32];
        __shared__ __align__(16) float buf[128*32];
        int j = blockIdx.x & 63, h = blockIdx.x >> 6;
        int n0 = j*NQ, w0 = j*NQ - 48, hd0 = h*CHD;
        for (int idx = t; idx < 32*32; idx += 128){
            int i = idx >> 5, d = idx & 31;
            qs[i][d] = g_q[(size_t)(n0+i)*CDIM + hd0 + d];
        }
        for (int idx = t; idx < 128*32; idx += 128){
            int m = idx >> 5, d = idx & 31;
            int key = w0 + m;
            float kk = 0.f, vv = 0.f;
            if (key >= 0 && key < NATOM){
                kk = g_k[(size_t)key*CDIM + hd0 + d];
                vv = g_v[(size_t)key*CDIM + hd0 + d];
            }
            buf[m*32 + d] = kk; vs[m][d] = vv;
        }
        __syncthreads();
        float kr[32];
        #pragma unroll
        for (int d = 0; d < 32; d++) kr[d] = buf[t*32 + d];
        __syncthreads();
        const float scale = 0.17677669529663687f;
        const float* pbr = pb + (size_t)h*NATOM*NKEY + (size_t)n0*NKEY;
        #pragma unroll 4
        for (int i = 0; i < 32; i++){
            float acc = 0.f;
            #pragma unroll
            for (int d4 = 0; d4 < 8; d4++){
                float4 q = *(const float4*)&qs[i][d4*4];
                acc = fmaf(q.x, kr[d4*4+0], fmaf(q.y, kr[d4*4+1],
                      fmaf(q.z, kr[d4*4+2], fmaf(q.w, kr[d4*4+3], acc))));
            }
            buf[i*128 + t] = acc*scale + pbr[i*NKEY + t];
        }
        __syncthreads();
        int w = t >> 5, l = t & 31;
        for (int r = 0; r < 8; r++){
            int i = w*8 + r;
            float x0=buf[i*128+l], x1=buf[i*128+l+32], x2=buf[i*128+l+64], x3=buf[i*128+l+96];
            float mx = fmaxf(fmaxf(x0,x1), fmaxf(x2,x3));
            #pragma unroll
            for (int o = 16; o; o >>= 1) mx = fmaxf(mx, __shfl_xor_sync(0xffffffffu, mx, o));
            float e0=expf(x0-mx), e1=expf(x1-mx), e2=expf(x2-mx), e3=expf(x3-mx);
            float s = e0+e1+e2+e3;
            #pragma unroll
            for (int o = 16; o; o >>= 1) s += __shfl_xor_sync(0xffffffffu, s, o);
            float inv = 1.f/s;
            buf[i*128+l]=e0*inv; buf[i*128+l+32]=e1*inv; buf[i*128+l+64]=e2*inv; buf[i*128+l+96]=e3*inv;
        }
        __syncthreads();
        int i = t >> 2, d0 = (t & 3)*8;
        float acc[8];
        #pragma unroll
        for (int dd = 0; dd < 8; dd++) acc[dd] = 0.f;
        #pragma unroll 4
        for (int kk = 0; kk < 128; kk++){
            float wgt = buf[i*128 + kk];
            float4 v0 = *(const float4*)&vs[kk][d0];
            float4 v1 = *(const float4*)&vs[kk][d0+4];
            acc[0] = fmaf(wgt, v0.x, acc[0]); acc[1] = fmaf(wgt, v0.y, acc[1]);
            acc[2] = fmaf(wgt, v0.z, acc[2]); acc[3] = fmaf(wgt, v0.w, acc[3]);
            acc[4] = fmaf(wgt, v1.x, acc[4]); acc[5] = fmaf(wgt, v1.y, acc[5]);
            acc[6] = fmaf(wgt, v1.z, acc[6]); acc[7] = fmaf(wgt, v1.w, acc[7]);
        }
        int n = n0 + i;
        #pragma unroll
        for (int dd = 0; dd < 8; dd++){
            int c = hd0 + d0 + dd;
            g_ob[(size_t)n*CDIM + c] = g_g[(size_t)n*CDIM + c]*acc[dd];
        }
    } else {
        __shared__ __align__(16) float a2s[8][CDIM];
        int m0 = (blockIdx.x - 256)*8;
        int w = t >> 5, l = t & 31;
        for (int idx = t; idx < 8*32; idx += 128){
            int r = idx >> 5, c4 = idx & 31;
            *(float4*)&a2s[r][c4*4] = *(const float4*)(g_a + (size_t)(m0+r)*CDIM + c4*4);
        }
        __syncthreads();
        for (int r2 = 0; r2 < 2; r2++){
            int i = w*2 + r2; int n = m0 + i;
            float x0=a2s[i][l], x1=a2s[i][l+32], x2=a2s[i][l+64], x3=a2s[i][l+96];
            float s = x0+x1+x2+x3;
            float s2 = x0*x0+x1*x1+x2*x2+x3*x3;
            #pragma unroll
            for (int o = 16; o; o >>= 1){
                s  += __shfl_xor_sync(0xffffffffu, s, o);
                s2 += __shfl_xor_sync(0xffffffffu, s2, o);
            }
            float mean = s*(1.f/CDIM);
            float var  = s2*(1.f/CDIM) - mean*mean;
            float rstd = rsqrtf(var + EPS);
            size_t nb = (size_t)n*CDIM;
            a2s[i][l]    = gate2[nb+l]   *((x0-mean)*rstd) + shift2[nb+l];
            a2s[i][l+32] = gate2[nb+l+32]*((x1-mean)*rstd) + shift2[nb+l+32];
            a2s[i][l+64] = gate2[nb+l+64]*((x2-mean)*rstd) + shift2[nb+l+64];
            a2s[i][l+96] = gate2[nb+l+96]*((x3-mean)*rstd) + shift2[nb+l+96];
        }
        __syncthreads();
        int c0 = t*2;
        float a10[8], a11[8], a20[8], a21[8];
        #pragma unroll
        for (int i = 0; i < 8; i++){ a10[i]=0.f; a11[i]=0.f; a20[i]=0.f; a21[i]=0.f; }
        for (int k4 = 0; k4 < CDIM/4; k4++){
            float2 p10 = *(const float2*)&wt1[(k4*4+0)*NHID + c0];
            float2 p11 = *(const float2*)&wt1[(k4*4+1)*NHID + c0];
            float2 p12 = *(const float2*)&wt1[(k4*4+2)*NHID + c0];
            float2 p13 = *(const float2*)&wt1[(k4*4+3)*NHID + c0];
            float2 p20 = *(const float2*)&wt2[(k4*4+0)*NHID + c0];
            float2 p21 = *(const float2*)&wt2[(k4*4+1)*NHID + c0];
            float2 p22 = *(const float2*)&wt2[(k4*4+2)*NHID + c0];
            float2 p23 = *(const float2*)&wt2[(k4*4+3)*NHID + c0];
            #pragma unroll
            for (int i = 0; i < 8; i++){
                float4 a = *(const float4*)&a2s[i][k4*4];
                a10[i] = fmaf(a.x, p10.x, fmaf(a.y, p11.x, fmaf(a.z, p12.x, fmaf(a.w, p13.x, a10[i]))));
                a11[i] = fmaf(a.x, p10.y, fmaf(a.y, p11.y, fmaf(a.z, p12.y, fmaf(a.w, p13.y, a11[i]))));
                a20[i] = fmaf(a.x, p20.x, fmaf(a.y, p21.x, fmaf(a.z, p22.x, fmaf(a.w, p23.x, a20[i]))));
                a21[i] = fmaf(a.x, p20.y, fmaf(a.y, p21.y, fmaf(a.z, p22.y, fmaf(a.w, p23.y, a21[i]))));
            }
        }
        #pragma unroll
        for (int i = 0; i < 8; i++){
            float h0 = a10[i], h1 = a11[i];
            float* o = g_hidden + (size_t)(m0+i)*NHID + c0;
            o[0] = h0*sigm(h0)*a20[i];
            o[1] = h1*sigm(h1)*a21[i];
        }
    }
}

// ---------------- light tail -> outp (g_a or d_out) --------------------------------
__global__ void tail_kernel(const float* __restrict__ wo, const float* __restrict__ og1,
                            const float* __restrict__ wt3, const float* __restrict__ og2,
                            float* __restrict__ outp){
    __shared__ __align__(16) float obs[8][CDIM];
    __shared__ __align__(16) float hid[8][NHID];
    int t = threadIdx.x;
    int m0 = blockIdx.x*8;
    for (int idx = t; idx < 8*CDIM/4; idx += 256){
        int r = idx >> 5, c4 = idx & 31;
        *(float4*)&obs[r][c4*4] = *(const float4*)(g_ob + (size_t)(m0+r)*CDIM + c4*4);
    }
    for (int idx = t; idx < 8*NHID/4; idx += 256){
        int r = idx >> 6, c4 = idx & 63;
        *(float4*)&hid[r][c4*4] = *(const float4*)(g_hidden + (size_t)(m0+r)*NHID + c4*4);
    }
    __syncthreads();
    int col = t & 127, half = t >> 7;
    int r0 = half*4;
    float attr[4];
    {
        float acc[4] = {0.f,0.f,0.f,0.f};
        #pragma unroll 2
        for (int k4 = 0; k4 < CDIM/4; k4++){
            float w0 = wo[(k4*4+0)*CDIM + col];
            float w1 = wo[(k4*4+1)*CDIM + col];
            float w2 = wo[(k4*4+2)*CDIM + col];
            float w3 = wo[(k4*4+3)*CDIM + col];
            #pragma unroll
            for (int i = 0; i < 4; i++){
                float4 a = *(const float4*)&obs[r0+i][k4*4];
                acc[i] = fmaf(a.x, w0, fmaf(a.y, w1, fmaf(a.z, w2, fmaf(a.w, w3, acc[i]))));
            }
        }
        size_t ob = (size_t)(m0+r0)*CDIM + col;
        attr[0] = og1[ob         ]*acc[0];
        attr[1] = og1[ob +   CDIM]*acc[1];
        attr[2] = og1[ob + 2*CDIM]*acc[2];
        attr[3] = og1[ob + 3*CDIM]*acc[3];
    }
    {
        float acc[4] = {0.f,0.f,0.f,0.f};
        #pragma unroll 2
        for (int k4 = 0; k4 < NHID/4; k4++){
            float w0 = wt3[(k4*4+0)*CDIM + col];
            float w1 = wt3[(k4*4+1)*CDIM + col];
            float w2 = wt3[(k4*4+2)*CDIM + col];
            float w3 = wt3[(k4*4+3)*CDIM + col];
            #pragma unroll
            for (int i = 0; i < 4; i++){
                float4 a = *(const float4*)&hid[r0+i][k4*4];
                acc[i] = fmaf(a.x, w0, fmaf(a.y, w1, fmaf(a.z, w2, fmaf(a.w, w3, acc[i]))));
            }
        }
        size_t ob = (size_t)(m0+r0)*CDIM + col;
        outp[ob         ] = attr[0] + og2[ob         ]*acc[0];
        outp[ob +   CDIM] = attr[1] + og2[ob +   CDIM]*acc[1];
        outp[ob + 2*CDIM] = attr[2] + og2[ob + 2*CDIM]*acc[2];
        outp[ob + 3*CDIM] = attr[3] + og2[ob + 3*CDIM]*acc[3];
    }
}

// ---------------- host launcher ----------------
extern "C" void kernel_launch(void* const* d_in, const int* in_sizes, int n_in,
                              void* d_out, int out_size){
    const float* ql       = (const float*)d_in[0];
    const float* cl       = (const float*)d_in[1];
    const float* plm      = (const float*)d_in[2];
    const float* a2t      = (const float*)d_in[3];
    const float* tm       = (const float*)d_in[4];
    const float* ada1_gs  = (const float*)d_in[5];
    const float* ada1_ws  = (const float*)d_in[6];
    const float* ada1_bs  = (const float*)d_in[7];
    const float* ada1_wsb = (const float*)d_in[8];
    const float* wq       = (const float*)d_in[9];
    const float* bq       = (const float*)d_in[10];
    const float* wk       = (const float*)d_in[11];
    const float* wv       = (const float*)d_in[12];
    const float* gz       = (const float*)d_in[13];
    const float* bz       = (const float*)d_in[14];
    const float* wz       = (const float*)d_in[15];
    const float* wg       = (const float*)d_in[16];
    const float* wo       = (const float*)d_in[17];
    const float* wog1     = (const float*)d_in[18];
    const float* bog1     = (const float*)d_in[19];
    const float* ada2_gs  = (const float*)d_in[20];
    const float* ada2_ws  = (const float*)d_in[21];
    const float* ada2_bs  = (const float*)d_in[22];
    const float* ada2_wsb = (const float*)d_in[23];
    const float* wt1      = (const float*)d_in[24];
    const float* wt2      = (const float*)d_in[25];
    const float* wt3      = (const float*)d_in[26];
    const float* wog2     = (const float*)d_in[27];
    const float* bog2     = (const float*)d_in[28];

    float *p_gate1, *p_shift1, *p_gate2, *p_shift2, *p_og1, *p_og2, *p_pb, *p_a;
    cudaGetSymbolAddress((void**)&p_gate1,  g_gate1);
    cudaGetSymbolAddress((void**)&p_shift1, g_shift1);
    cudaGetSymbolAddress((void**)&p_gate2,  g_gate2);
    cudaGetSymbolAddress((void**)&p_shift2, g_shift2);
    cudaGetSymbolAddress((void**)&p_og1,    g_og1);
    cudaGetSymbolAddress((void**)&p_og2,    g_og2);
    cudaGetSymbolAddress((void**)&p_pb,     g_pb);
    cudaGetSymbolAddress((void**)&p_a,      g_a);

    prep_kernel<<<COPY_CTAS + MB_CTAS, 256>>>(ql, a2t, tm);

    stage2_kernel<<<PRE_CTAS + PB_CTAS, 128>>>(cl, plm, gz, bz, wz,
        ada1_gs, ada1_ws, ada1_bs, ada1_wsb,
        ada2_gs, ada2_ws, ada2_bs, ada2_wsb,
        wog1, bog1, wog2, bog2);

    for (int b = 0; b < NBL; b++){
        size_t oC = (size_t)b*NC, oW = (size_t)b*CDIM*CDIM;
        dim3 qg(NATOM/16, 4);
        adaln_proj_kernel<<<qg, 128>>>(p_gate1+oC, p_shift1+oC,
                                       wq+oW, bq+(size_t)b*CDIM, wk+oW, wv+oW, wg+oW);
        mid_kernel<<<256 + NATOM/8, 128>>>(p_pb + (size_t)b*NHEADS*NATOM*NKEY,
                                           p_gate2+oC, p_shift2+oC,
                                           wt1+(size_t)b*CDIM*NHID, wt2+(size_t)b*CDIM*NHID);
        float* outp = (b == NBL-1) ? (float*)d_out : p_a;
        tail_kernel<<<NATOM/8, 256>>>(wo+oW, p_og1+oC,
                                      wt3+(size_t)b*NHID*CDIM, p_og2+oC, outp);
    }
}

// round 10
// speedup vs baseline: 1.3404x; 1.1397x over previous
#include <cuda_runtime.h>
#include <math.h>

#define NATOM 2048
#define NTOK  512
#define CDIM  128
#define CZD   16
#define NHEADS 4
#define CHD   32
#define NBL   3
#define NHID  256
#define NQ    32
#define NKEY  128
#define NQB   (NATOM/NQ)
#define EPS   1e-5f
#define NEGBIG -1e30f
#define NC    (NATOM*CDIM)

#define COPY_CTAS (NC/256)
#define MB_CTAS   (NATOM/8)
#define PRE_CTAS  (18*64)
#define PB_CTAS   NATOM

// ---------------- scratch ----------------
__device__ float g_maskbias[NATOM];
__device__ float g_gate1[NBL*NC];
__device__ float g_shift1[NBL*NC];
__device__ float g_gate2[NBL*NC];
__device__ float g_shift2[NBL*NC];
__device__ float g_og1[NBL*NC];
__device__ float g_og2[NBL*NC];
__device__ float g_pb[NBL*NHEADS*NATOM*NKEY];
__device__ float g_a[NC];
__device__ float g_q[NC];
__device__ float g_k[NC];
__device__ float g_v[NC];
__device__ float g_g[NC];
__device__ float g_ob[NC];
__device__ float g_hidden[NATOM*NHID];

__device__ __forceinline__ float sigm(float x){ return 1.f/(1.f+expf(-x)); }

// ---------------- prep: copy_in + maskbias ----------------
__global__ void prep_kernel(const float* __restrict__ ql,
                            const float* __restrict__ a2t, const float* __restrict__ tm){
    int x = blockIdx.x, t = threadIdx.x;
    if (x < COPY_CTAS){
        int i = x*256 + t;
        g_a[i] = ql[i];
    } else {
        int w = t >> 5, l = t & 31;
        int n = (x - COPY_CTAS)*8 + w;
        const float* row = a2t + (size_t)n*NTOK;
        float s = 0.f;
        for (int i = l; i < NTOK; i += 32) s += row[i]*tm[i];
        #pragma unroll
        for (int o = 16; o; o >>= 1) s += __shfl_xor_sync(0xffffffffu, s, o);
        if (l == 0) g_maskbias[n] = (s - 1.0f)*1e9f;
    }
}

// ---------------- stage2: 18 precompute GEMMs (LN inline) UNION pair-bias ----------
__global__ void __launch_bounds__(128) stage2_kernel(
    const float* __restrict__ cl, const float* __restrict__ plm,
    const float* __restrict__ gz, const float* __restrict__ bz, const float* __restrict__ wz,
    const float* __restrict__ a1gs, const float* __restrict__ a1ws,
    const float* __restrict__ a1bs, const float* __restrict__ a1wsb,
    const float* __restrict__ a2gs, const float* __restrict__ a2ws,
    const float* __restrict__ a2bs, const float* __restrict__ a2wsb,
    const float* __restrict__ wog1, const float* __restrict__ bog1,
    const float* __restrict__ wog2, const float* __restrict__ bog2)
{
    int t = threadIdx.x;
    if (blockIdx.x < PRE_CTAS){
        int my = blockIdx.x / 64;
        int tile = blockIdx.x % 64;
        int b = my/6, m = my%6;
        size_t oW = (size_t)b*CDIM*CDIM, o1 = (size_t)b*CDIM, oC = (size_t)b*NC;
        const float* gs = 0; const float* W = 0;
        const float* bias = 0; float* out = 0; int sig = 0; int doLN = (m < 4);
        switch(m){
            case 0: gs=a1gs+o1; W=a1ws +oW; bias=a1bs+o1; sig=1; out=g_gate1 +oC; break;
            case 1: gs=a1gs+o1; W=a1wsb+oW;               sig=0; out=g_shift1+oC; break;
            case 2: gs=a2gs+o1; W=a2ws +oW; bias=a2bs+o1; sig=1; out=g_gate2 +oC; break;
            case 3: gs=a2gs+o1; W=a2wsb+oW;               sig=0; out=g_shift2+oC; break;
            case 4: W=wog1+oW; bias=bog1+o1; sig=1; out=g_og1+oC; break;
            default: W=wog2+oW; bias=bog2+o1; sig=1; out=g_og2+oC; break;
        }
        __shared__ __align__(16) float ins[32][CDIM];
        int m0 = tile*32;
        const float4* in4 = (const float4*)cl;
        for (int idx = t; idx < 32*32; idx += 128){
            int r = idx >> 5, c4 = idx & 31;
            *(float4*)&ins[r][c4*4] = in4[(size_t)(m0+r)*32 + c4];
        }
        __syncthreads();
        if (doLN){
            int w = t >> 5, l = t & 31;
            for (int r8 = 0; r8 < 8; r8++){
                int r = w*8 + r8;
                float x0=ins[r][l], x1=ins[r][l+32], x2=ins[r][l+64], x3=ins[r][l+96];
                float s = x0+x1+x2+x3;
                float s2 = x0*x0+x1*x1+x2*x2+x3*x3;
                #pragma unroll
                for (int o = 16; o; o >>= 1){
                    s  += __shfl_xor_sync(0xffffffffu, s, o);
                    s2 += __shfl_xor_sync(0xffffffffu, s2, o);
                }
                float mean = s*(1.f/CDIM);
                float var  = s2*(1.f/CDIM) - mean*mean;
                float rstd = rsqrtf(var + EPS);
                ins[r][l]    = (x0-mean)*rstd*gs[l];
                ins[r][l+32] = (x1-mean)*rstd*gs[l+32];
                ins[r][l+64] = (x2-mean)*rstd*gs[l+64];
                ins[r][l+96] = (x3-mean)*rstd*gs[l+96];
            }
            __syncthreads();
        }
        int c0 = (t & 63)*2;
        int rg = (t >> 6)*16;
        float acc0[16], acc1[16];
        #pragma unroll
        for (int i = 0; i < 16; i++){ acc0[i]=0.f; acc1[i]=0.f; }
        for (int k4 = 0; k4 < CDIM/4; k4++){
            float2 w0 = *(const float2*)&W[(k4*4+0)*CDIM + c0];
            float2 w1 = *(const float2*)&W[(k4*4+1)*CDIM + c0];
            float2 w2 = *(const float2*)&W[(k4*4+2)*CDIM + c0];
            float2 w3 = *(const float2*)&W[(k4*4+3)*CDIM + c0];
            #pragma unroll
            for (int i = 0; i < 16; i++){
                float4 a = *(const float4*)&ins[rg+i][k4*4];
                acc0[i] = fmaf(a.x, w0.x, fmaf(a.y, w1.x, fmaf(a.z, w2.x, fmaf(a.w, w3.x, acc0[i]))));
                acc1[i] = fmaf(a.x, w0.y, fmaf(a.y, w1.y, fmaf(a.z, w2.y, fmaf(a.w, w3.y, acc1[i]))));
            }
        }
        float b0 = bias ? bias[c0] : 0.f;
        float b1 = bias ? bias[c0+1] : 0.f;
        #pragma unroll
        for (int i = 0; i < 16; i++){
            float v0 = acc0[i] + b0, v1 = acc1[i] + b1;
            if (sig){ v0 = sigm(v0); v1 = sigm(v1); }
            float* o = out + (size_t)(m0+rg+i)*CDIM + c0;
            o[0] = v0; o[1] = v1;
        }
    } else {
        __shared__ float wzc[CZD][12];
        __shared__ float bzd[12];
        for (int idx = t; idx < CZD*12; idx += 128){
            int c = idx/12, id = idx%12, b = id>>2, h = id&3;
            wzc[c][id] = gz[b*CZD + c]*wz[(b*CZD + c)*4 + h];
        }
        if (t < 12){
            int b = t>>2, h = t&3; float s = 0.f;
            for (int c = 0; c < CZD; c++) s += bz[b*CZD + c]*wz[(b*CZD + c)*4 + h];
            bzd[t] = s;
        }
        __syncthreads();
        int n = blockIdx.x - PRE_CTAS;
        int slot = t;
        int m = (n & ~31) - 48 + slot;
        if (m < 0 || m >= NATOM){
            #pragma unroll
            for (int idx = 0; idx < 12; idx++)
                g_pb[((size_t)idx*NATOM + n)*NKEY + slot] = NEGBIG;
            return;
        }
        const float4* p = (const float4*)(plm + ((size_t)n*NATOM + m)*CZD);
        float x[16];
        float4 f;
        f = p[0]; x[0]=f.x; x[1]=f.y; x[2]=f.z; x[3]=f.w;
        f = p[1]; x[4]=f.x; x[5]=f.y; x[6]=f.z; x[7]=f.w;
        f = p[2]; x[8]=f.x; x[9]=f.y; x[10]=f.z; x[11]=f.w;
        f = p[3]; x[12]=f.x; x[13]=f.y; x[14]=f.z; x[15]=f.w;
        float s = 0.f, s2 = 0.f;
        #pragma unroll
        for (int c = 0; c < 16; c++){ s += x[c]; s2 += x[c]*x[c]; }
        float mean = s*(1.f/16.f);
        float var  = s2*(1.f/16.f) - mean*mean;
        float rstd = rsqrtf(var + EPS);
        float val[12];
        #pragma unroll
        for (int idx = 0; idx < 12; idx++) val[idx] = 0.f;
        #pragma unroll
        for (int c = 0; c < 16; c++){
            float z = (x[c]-mean)*rstd;
            #pragma unroll
            for (int idx = 0; idx < 12; idx++) val[idx] += z*wzc[c][idx];
        }
        float mb = g_maskbias[m];
        #pragma unroll
        for (int idx = 0; idx < 12; idx++)
            g_pb[((size_t)idx*NATOM + n)*NKEY + slot] = val[idx] + bzd[idx] + mb;
    }
}

// ---------------- per-block: AdaLN + {q,k,v,g}, 256 threads ------------------------
__global__ void __launch_bounds__(256) adaln_proj_kernel(
                                  const float* __restrict__ gate1, const float* __restrict__ shift1,
                                  const float* __restrict__ wq, const float* __restrict__ bq,
                                  const float* __restrict__ wk, const float* __restrict__ wv,
                                  const float* __restrict__ wg){
    __shared__ __align__(16) float als[16][CDIM];
    int t = threadIdx.x; int m0 = blockIdx.x*16;
    int mat = blockIdx.y;
    int w = t >> 5, l = t & 31;
    for (int idx = t; idx < 16*32; idx += 256){
        int r = idx >> 5, c4 = idx & 31;
        *(float4*)&als[r][c4*4] = *(const float4*)(g_a + (size_t)(m0+r)*CDIM + c4*4);
    }
    __syncthreads();
    for (int r = 0; r < 2; r++){
        int i = w*2 + r; int n = m0 + i;
        float x0=als[i][l], x1=als[i][l+32], x2=als[i][l+64], x3=als[i][l+96];
        float s = x0+x1+x2+x3;
        float s2 = x0*x0+x1*x1+x2*x2+x3*x3;
        #pragma unroll
        for (int o = 16; o; o >>= 1){
            s  += __shfl_xor_sync(0xffffffffu, s, o);
            s2 += __shfl_xor_sync(0xffffffffu, s2, o);
        }
        float mean = s*(1.f/CDIM);
        float var  = s2*(1.f/CDIM) - mean*mean;
        float rstd = rsqrtf(var + EPS);
        float a0=(x0-mean)*rstd, a1=(x1-mean)*rstd, a2=(x2-mean)*rstd, a3=(x3-mean)*rstd;
        size_t nb = (size_t)n*CDIM;
        als[i][l]    = gate1[nb+l]   *a0 + shift1[nb+l];
        als[i][l+32] = gate1[nb+l+32]*a1 + shift1[nb+l+32];
        als[i][l+64] = gate1[nb+l+64]*a2 + shift1[nb+l+64];
        als[i][l+96] = gate1[nb+l+96]*a3 + shift1[nb+l+96];
    }
    __syncthreads();
    const float* W; float* O;
    switch(mat){
        case 0: W = wq; O = g_q; break;
        case 1: W = wk; O = g_k; break;
        case 2: W = wv; O = g_v; break;
        default: W = wg; O = g_g; break;
    }
    int col = t & 127;
    int rg = (t >> 7)*8;       // 0 or 8
    float acc[8];
    #pragma unroll
    for (int i = 0; i < 8; i++) acc[i] = 0.f;
    #pragma unroll 2
    for (int k4 = 0; k4 < CDIM/4; k4++){
        float w0 = W[(k4*4+0)*CDIM + col];
        float w1 = W[(k4*4+1)*CDIM + col];
        float w2 = W[(k4*4+2)*CDIM + col];
        float w3 = W[(k4*4+3)*CDIM + col];
        #pragma unroll
        for (int i = 0; i < 8; i++){
            float4 a = *(const float4*)&als[rg+i][k4*4];
            acc[i] = fmaf(a.x, w0, fmaf(a.y, w1, fmaf(a.z, w2, fmaf(a.w, w3, acc[i]))));
        }
    }
    float bb = (mat == 0) ? bq[col] : 0.f;
    #pragma unroll
    for (int i = 0; i < 8; i++){
        float v = acc[i] + bb;
        if (mat == 3) v = sigm(v);
        O[(size_t)(m0+rg+i)*CDIM + col] = v;
    }
}

// ---------------- union: attention (x<256) + trans1 (x>=256), 256 threads ----------
__global__ void __launch_bounds__(256) mid_kernel(const float* __restrict__ pb,
                           const float* __restrict__ gate2, const float* __restrict__ shift2,
                           const float* __restrict__ wt1, const float* __restrict__ wt2){
    int t = threadIdx.x;
    if (blockIdx.x < 256){
        __shared__ __align__(16) float qs[32][32];
        __shared__ __align__(16) float vs[128][32];
        __shared__ __align__(16) float buf[128*32];
        int j = blockIdx.x & 63, h = blockIdx.x >> 6;
        int n0 = j*NQ, w0 = j*NQ - 48, hd0 = h*CHD;
        for (int idx = t; idx < 32*32; idx += 256){
            int i = idx >> 5, d = idx & 31;
            qs[i][d] = g_q[(size_t)(n0+i)*CDIM + hd0 + d];
        }
        for (int idx = t; idx < 128*32; idx += 256){
            int m = idx >> 5, d = idx & 31;
            int key = w0 + m;
            float kk = 0.f, vv = 0.f;
            if (key >= 0 && key < NATOM){
                kk = g_k[(size_t)key*CDIM + hd0 + d];
                vv = g_v[(size_t)key*CDIM + hd0 + d];
            }
            buf[m*32 + d] = kk; vs[m][d] = vv;
        }
        __syncthreads();
        int key = t & 127, qh = t >> 7;     // thread-halves split queries
        float kr[32];
        #pragma unroll
        for (int d = 0; d < 32; d++) kr[d] = buf[key*32 + d];
        __syncthreads();
        const float scale = 0.17677669529663687f;
        const float* pbr = pb + (size_t)h*NATOM*NKEY + (size_t)n0*NKEY;
        #pragma unroll 4
        for (int i2 = 0; i2 < 16; i2++){
            int i = qh*16 + i2;
            float acc = 0.f;
            #pragma unroll
            for (int d4 = 0; d4 < 8; d4++){
                float4 q = *(const float4*)&qs[i][d4*4];
                acc = fmaf(q.x, kr[d4*4+0], fmaf(q.y, kr[d4*4+1],
                      fmaf(q.z, kr[d4*4+2], fmaf(q.w, kr[d4*4+3], acc))));
            }
            buf[i*128 + key] = acc*scale + pbr[i*NKEY + key];
        }
        __syncthreads();
        int w = t >> 5, l = t & 31;
        for (int r = 0; r < 4; r++){        // 8 warps x 4 rows
            int i = w*4 + r;
            float x0=buf[i*128+l], x1=buf[i*128+l+32], x2=buf[i*128+l+64], x3=buf[i*128+l+96];
            float mx = fmaxf(fmaxf(x0,x1), fmaxf(x2,x3));
            #pragma unroll
            for (int o = 16; o; o >>= 1) mx = fmaxf(mx, __shfl_xor_sync(0xffffffffu, mx, o));
            float e0=expf(x0-mx), e1=expf(x1-mx), e2=expf(x2-mx), e3=expf(x3-mx);
            float s = e0+e1+e2+e3;
            #pragma unroll
            for (int o = 16; o; o >>= 1) s += __shfl_xor_sync(0xffffffffu, s, o);
            float inv = 1.f/s;
            buf[i*128+l]=e0*inv; buf[i*128+l+32]=e1*inv; buf[i*128+l+64]=e2*inv; buf[i*128+l+96]=e3*inv;
        }
        __syncthreads();
        int i = t >> 3, d0 = (t & 7)*4;     // 32 queries x 4 dims per thread
        float acc[4] = {0.f,0.f,0.f,0.f};
        #pragma unroll 4
        for (int kk = 0; kk < 128; kk++){
            float wgt = buf[i*128 + kk];
            float4 v = *(const float4*)&vs[kk][d0];
            acc[0] = fmaf(wgt, v.x, acc[0]); acc[1] = fmaf(wgt, v.y, acc[1]);
            acc[2] = fmaf(wgt, v.z, acc[2]); acc[3] = fmaf(wgt, v.w, acc[3]);
        }
        int n = n0 + i;
        #pragma unroll
        for (int dd = 0; dd < 4; dd++){
            int c = hd0 + d0 + dd;
            g_ob[(size_t)n*CDIM + c] = g_g[(size_t)n*CDIM + c]*acc[dd];
        }
    } else {
        __shared__ __align__(16) float a2s[8][CDIM];
        int m0 = (blockIdx.x - 256)*8;
        int w = t >> 5, l = t & 31;
        if (t < 256){
            int r = t >> 5, c4 = t & 31;
            *(float4*)&a2s[r][c4*4] = *(const float4*)(g_a + (size_t)(m0+r)*CDIM + c4*4);
        }
        __syncthreads();
        {
            int i = w; int n = m0 + i;      // 8 warps x 1 row
            float x0=a2s[i][l], x1=a2s[i][l+32], x2=a2s[i][l+64], x3=a2s[i][l+96];
            float s = x0+x1+x2+x3;
            float s2 = x0*x0+x1*x1+x2*x2+x3*x3;
            #pragma unroll
            for (int o = 16; o; o >>= 1){
                s  += __shfl_xor_sync(0xffffffffu, s, o);
                s2 += __shfl_xor_sync(0xffffffffu, s2, o);
            }
            float mean = s*(1.f/CDIM);
            float var  = s2*(1.f/CDIM) - mean*mean;
            float rstd = rsqrtf(var + EPS);
            size_t nb = (size_t)n*CDIM;
            a2s[i][l]    = gate2[nb+l]   *((x0-mean)*rstd) + shift2[nb+l];
            a2s[i][l+32] = gate2[nb+l+32]*((x1-mean)*rstd) + shift2[nb+l+32];
            a2s[i][l+64] = gate2[nb+l+64]*((x2-mean)*rstd) + shift2[nb+l+64];
            a2s[i][l+96] = gate2[nb+l+96]*((x3-mean)*rstd) + shift2[nb+l+96];
        }
        __syncthreads();
        int c = t;                           // one hidden column per thread
        float a1[8], a2r[8];
        #pragma unroll
        for (int i = 0; i < 8; i++){ a1[i]=0.f; a2r[i]=0.f; }
        #pragma unroll 2
        for (int k4 = 0; k4 < CDIM/4; k4++){
            float w10 = wt1[(k4*4+0)*NHID + c], w20 = wt2[(k4*4+0)*NHID + c];
            float w11 = wt1[(k4*4+1)*NHID + c], w21 = wt2[(k4*4+1)*NHID + c];
            float w12 = wt1[(k4*4+2)*NHID + c], w22 = wt2[(k4*4+2)*NHID + c];
            float w13 = wt1[(k4*4+3)*NHID + c], w23 = wt2[(k4*4+3)*NHID + c];
            #pragma unroll
            for (int i = 0; i < 8; i++){
                float4 a = *(const float4*)&a2s[i][k4*4];
                a1[i]  = fmaf(a.x, w10, fmaf(a.y, w11, fmaf(a.z, w12, fmaf(a.w, w13, a1[i]))));
                a2r[i] = fmaf(a.x, w20, fmaf(a.y, w21, fmaf(a.z, w22, fmaf(a.w, w23, a2r[i]))));
            }
        }
        #pragma unroll
        for (int i = 0; i < 8; i++){
            float h1 = a1[i];
            g_hidden[(size_t)(m0+i)*NHID + c] = h1*sigm(h1)*a2r[i];
        }
    }
}

// ---------------- light tail: 4 rows, 512 CTAs -> outp ----------------------------
__global__ void __launch_bounds__(256) tail_kernel(
                            const float* __restrict__ wo, const float* __restrict__ og1,
                            const float* __restrict__ wt3, const float* __restrict__ og2,
                            float* __restrict__ outp){
    __shared__ __align__(16) float obs[4][CDIM];
    __shared__ __align__(16) float hid[4][NHID];
    int t = threadIdx.x;
    int m0 = blockIdx.x*4;
    if (t < 128){
        int r = t >> 5, c4 = t & 31;
        *(float4*)&obs[r][c4*4] = *(const float4*)(g_ob + (size_t)(m0+r)*CDIM + c4*4);
    }
    {
        int r = t >> 6, c4 = t & 63;
        *(float4*)&hid[r][c4*4] = *(const float4*)(g_hidden + (size_t)(m0+r)*NHID + c4*4);
    }
    __syncthreads();
    int col = t & 127, half = t >> 7;
    int r0 = half*2;
    float attr[2];
    {
        float acc[2] = {0.f,0.f};
        #pragma unroll 2
        for (int k4 = 0; k4 < CDIM/4; k4++){
            float w0 = wo[(k4*4+0)*CDIM + col];
            float w1 = wo[(k4*4+1)*CDIM + col];
            float w2 = wo[(k4*4+2)*CDIM + col];
            float w3 = wo[(k4*4+3)*CDIM + col];
            #pragma unroll
            for (int i = 0; i < 2; i++){
                float4 a = *(const float4*)&obs[r0+i][k4*4];
                acc[i] = fmaf(a.x, w0, fmaf(a.y, w1, fmaf(a.z, w2, fmaf(a.w, w3, acc[i]))));
            }
        }
        size_t ob = (size_t)(m0+r0)*CDIM + col;
        attr[0] = og1[ob       ]*acc[0];
        attr[1] = og1[ob + CDIM]*acc[1];
    }
    {
        float acc[2] = {0.f,0.f};
        #pragma unroll 2
        for (int k4 = 0; k4 < NHID/4; k4++){
            float w0 = wt3[(k4*4+0)*CDIM + col];
            float w1 = wt3[(k4*4+1)*CDIM + col];
            float w2 = wt3[(k4*4+2)*CDIM + col];
            float w3 = wt3[(k4*4+3)*CDIM + col];
            #pragma unroll
            for (int i = 0; i < 2; i++){
                float4 a = *(const float4*)&hid[r0+i][k4*4];
                acc[i] = fmaf(a.x, w0, fmaf(a.y, w1, fmaf(a.z, w2, fmaf(a.w, w3, acc[i]))));
            }
        }
        size_t ob = (size_t)(m0+r0)*CDIM + col;
        outp[ob       ] = attr[0] + og2[ob       ]*acc[0];
        outp[ob + CDIM] = attr[1] + og2[ob + CDIM]*acc[1];
    }
}

// ---------------- host launcher ----------------
extern "C" void kernel_launch(void* const* d_in, const int* in_sizes, int n_in,
                              void* d_out, int out_size){
    const float* ql       = (const float*)d_in[0];
    const float* cl       = (const float*)d_in[1];
    const float* plm      = (const float*)d_in[2];
    const float* a2t      = (const float*)d_in[3];
    const float* tm       = (const float*)d_in[4];
    const float* ada1_gs  = (const float*)d_in[5];
    const float* ada1_ws  = (const float*)d_in[6];
    const float* ada1_bs  = (const float*)d_in[7];
    const float* ada1_wsb = (const float*)d_in[8];
    const float* wq       = (const float*)d_in[9];
    const float* bq       = (const float*)d_in[10];
    const float* wk       = (const float*)d_in[11];
    const float* wv       = (const float*)d_in[12];
    const float* gz       = (const float*)d_in[13];
    const float* bz       = (const float*)d_in[14];
    const float* wz       = (const float*)d_in[15];
    const float* wg       = (const float*)d_in[16];
    const float* wo       = (const float*)d_in[17];
    const float* wog1     = (const float*)d_in[18];
    const float* bog1     = (const float*)d_in[19];
    const float* ada2_gs  = (const float*)d_in[20];
    const float* ada2_ws  = (const float*)d_in[21];
    const float* ada2_bs  = (const float*)d_in[22];
    const float* ada2_wsb = (const float*)d_in[23];
    const float* wt1      = (const float*)d_in[24];
    const float* wt2      = (const float*)d_in[25];
    const float* wt3      = (const float*)d_in[26];
    const float* wog2     = (const float*)d_in[27];
    const float* bog2     = (const float*)d_in[28];

    float *p_gate1, *p_shift1, *p_gate2, *p_shift2, *p_og1, *p_og2, *p_pb, *p_a;
    cudaGetSymbolAddress((void**)&p_gate1,  g_gate1);
    cudaGetSymbolAddress((void**)&p_shift1, g_shift1);
    cudaGetSymbolAddress((void**)&p_gate2,  g_gate2);
    cudaGetSymbolAddress((void**)&p_shift2, g_shift2);
    cudaGetSymbolAddress((void**)&p_og1,    g_og1);
    cudaGetSymbolAddress((void**)&p_og2,    g_og2);
    cudaGetSymbolAddress((void**)&p_pb,     g_pb);
    cudaGetSymbolAddress((void**)&p_a,      g_a);

    prep_kernel<<<COPY_CTAS + MB_CTAS, 256>>>(ql, a2t, tm);

    stage2_kernel<<<PRE_CTAS + PB_CTAS, 128>>>(cl, plm, gz, bz, wz,
        ada1_gs, ada1_ws, ada1_bs, ada1_wsb,
        ada2_gs, ada2_ws, ada2_bs, ada2_wsb,
        wog1, bog1, wog2, bog2);

    for (int b = 0; b < NBL; b++){
        size_t oC = (size_t)b*NC, oW = (size_t)b*CDIM*CDIM;
        dim3 qg(NATOM/16, 4);
        adaln_proj_kernel<<<qg, 256>>>(p_gate1+oC, p_shift1+oC,
                                       wq+oW, bq+(size_t)b*CDIM, wk+oW, wv+oW, wg+oW);
        mid_kernel<<<256 + NATOM/8, 256>>>(p_pb + (size_t)b*NHEADS*NATOM*NKEY,
                                           p_gate2+oC, p_shift2+oC,
                                           wt1+(size_t)b*CDIM*NHID, wt2+(size_t)b*CDIM*NHID);
        float* outp = (b == NBL-1) ? (float*)d_out : p_a;
        tail_kernel<<<NATOM/4, 256>>>(wo+oW, p_og1+oC,
                                      wt3+(size_t)b*NHID*CDIM, p_og2+oC, outp);
    }
}